// round 1
// baseline (speedup 1.0000x reference)
#include <cuda_runtime.h>
#include <math.h>

#define NU 200000
#define NI 200000
#define D  128
#define B  4096
#define KRNN 264   // [x(129) | h(128) | pad(7)]

// ---- output layout (flattened tuple, row-major) ----
#define OFF_PRED       0
#define OFF_TARGET     (B*2*D)
#define OFF_UPD_USER   (OFF_TARGET + B*2*D)
#define OFF_USER_EMB   (OFF_UPD_USER + B*D)
#define OFF_UPD_ITEM   (OFF_USER_EMB + B*D)
#define OFF_ITEM_EMB   (OFF_UPD_ITEM + B*D)
#define OFF_DYN_USER   (OFF_ITEM_EMB + B*D)
#define OFF_DYN_ITEM   (OFF_DYN_USER + NU*D)
#define OFF_ISNEW_U    (OFF_DYN_ITEM + NI*D)
#define OFF_ISNEW_I    (OFF_ISNEW_U + NU)

// ---- device scratch (no allocations allowed) ----
__device__ __align__(16) float g_Xpred[B * 512];
__device__ __align__(16) float g_Xu[B * KRNN];
__device__ __align__(16) float g_Xi[B * KRNN];
__device__ __align__(16) float g_Wu[D * KRNN];
__device__ __align__(16) float g_Wi[D * KRNN];
__device__ float g_bu[D];
__device__ float g_bi[D];
__device__ int g_winner_u[NU];
__device__ int g_winner_i[NI];

// ---------------------------------------------------------------------------
// reset winner arrays to -1 (must be full clear: graph replays reuse globals)
__global__ void reset_kernel() {
    int i = blockIdx.x * blockDim.x + threadIdx.x;
    if (i < NU) { g_winner_u[i] = -1; g_winner_i[i] = -1; }
}

// build combined RNN weights [Wih | Whh | 0] and fused biases
__global__ void prep_kernel(const float* __restrict__ uWih, const float* __restrict__ uWhh,
                            const float* __restrict__ ubih, const float* __restrict__ ubhh,
                            const float* __restrict__ iWih, const float* __restrict__ iWhh,
                            const float* __restrict__ ibih, const float* __restrict__ ibhh) {
    int i = blockIdx.x * blockDim.x + threadIdx.x;
    if (i < D * KRNN) {
        int n = i / KRNN, k = i % KRNN;
        float wu, wi;
        if (k < 129)      { wu = uWih[n * 129 + k];       wi = iWih[n * 129 + k]; }
        else if (k < 257) { wu = uWhh[n * 128 + (k-129)]; wi = iWhh[n * 128 + (k-129)]; }
        else              { wu = 0.f; wi = 0.f; }
        g_Wu[i] = wu; g_Wi[i] = wi;
    }
    if (i < D) { g_bu[i] = ubih[i] + ubhh[i]; g_bi[i] = ibih[i] + ibhh[i]; }
}

// ---------------------------------------------------------------------------
// per-row gathers, direct outputs, GEMM-input assembly, winner atomicMax
__global__ void gather_kernel(const int* __restrict__ uid, const int* __restrict__ pid,
                              const int* __restrict__ iid,
                              const float* __restrict__ t_item, const float* __restrict__ t_user,
                              const float* __restrict__ dynU, const float* __restrict__ dynI,
                              const float* __restrict__ isU, const float* __restrict__ isI,
                              const float* __restrict__ statU, const float* __restrict__ statI,
                              const float* __restrict__ initU, const float* __restrict__ initI,
                              const float* __restrict__ tdW, const float* __restrict__ tdb,
                              float* __restrict__ out) {
    int b = blockIdx.x;
    int d = threadIdx.x;           // 0..127
    int u = uid[b], p = pid[b], it = iid[b];
    float ti = t_item[b], tu = t_user[b];
    float fu = isU[u], fi = isI[it], fp = isI[p];

    float ue = fu * initU[d] + dynU[(long)u * D + d];
    float ie = fi * initI[d] + dynI[(long)it * D + d];
    float pe = fp * initI[d] + dynI[(long)p * D + d];
    float su = statU[(long)u * D + d];
    float si = statI[(long)it * D + d];
    float ps = statI[(long)p * D + d];

    out[OFF_USER_EMB + b * D + d] = ue;
    out[OFF_ITEM_EMB + b * D + d] = ie;
    out[OFF_TARGET + b * 2 * D + d]     = ie;
    out[OFF_TARGET + b * 2 * D + D + d] = si;

    // pred input X = [user_proj | prev_item_emb | prev_static_item | static_user]
    float proj = ue * (1.f + ti * tdW[d] + tdb[d]);
    g_Xpred[b * 512 + d]       = proj;
    g_Xpred[b * 512 + 128 + d] = pe;
    g_Xpred[b * 512 + 256 + d] = ps;
    g_Xpred[b * 512 + 384 + d] = su;

    // RNN inputs: Xu = [item_emb, ti, user_emb, pad]; Xi = [user_emb, tu, item_emb, pad]
    g_Xu[b * KRNN + d]       = ie;
    g_Xu[b * KRNN + 129 + d] = ue;
    g_Xi[b * KRNN + d]       = ue;
    g_Xi[b * KRNN + 129 + d] = ie;
    if (d == 0) {
        g_Xu[b * KRNN + 128] = ti;
        g_Xi[b * KRNN + 128] = tu;
        atomicMax(&g_winner_u[u], b);   // last occurrence wins (CPU scatter order)
        atomicMax(&g_winner_i[it], b);
    }
    if (d < KRNN - 257) {               // zero pad cols 257..263
        g_Xu[b * KRNN + 257 + d] = 0.f;
        g_Xi[b * KRNN + 257 + d] = 0.f;
    }
}

// ---------------------------------------------------------------------------
// C[m][n] = act( sum_k X[m][k]*W[n][k] + bias[n] )
// block tile 128(M) x 64(N), BK=8, 256 threads, 8x4 per-thread microtile
template <int KDIM, bool TANH>
__global__ void gemm_kernel(const float* __restrict__ X, const float* __restrict__ W,
                            const float* __restrict__ bias, float* __restrict__ C, int ldc) {
    __shared__ __align__(16) float As[8][128];
    __shared__ __align__(16) float Bs[8][64];
    int tid = threadIdx.x;
    int m0 = blockIdx.x * 128;
    int n0 = blockIdx.y * 64;
    int tx = tid & 15;        // N dir (x4)
    int ty = tid >> 4;        // M dir (x8)
    float acc[8][4] = {};

    int arow = tid >> 1;            // 0..127
    int acol = (tid & 1) * 4;       // 0 or 4
    const int KT = (KDIM + 7) / 8;

    for (int kt = 0; kt < KT; kt++) {
        int k0 = kt * 8;
        float4 av = *(const float4*)&X[(long)(m0 + arow) * KDIM + k0 + acol];
        As[acol + 0][arow] = av.x; As[acol + 1][arow] = av.y;
        As[acol + 2][arow] = av.z; As[acol + 3][arow] = av.w;
        if (tid < 128) {
            int brow = tid >> 1, bcol = (tid & 1) * 4;
            float4 bv = *(const float4*)&W[(long)(n0 + brow) * KDIM + k0 + bcol];
            Bs[bcol + 0][brow] = bv.x; Bs[bcol + 1][brow] = bv.y;
            Bs[bcol + 2][brow] = bv.z; Bs[bcol + 3][brow] = bv.w;
        }
        __syncthreads();
        #pragma unroll
        for (int k = 0; k < 8; k++) {
            float4 a0 = *(const float4*)&As[k][ty * 8];
            float4 a1 = *(const float4*)&As[k][ty * 8 + 4];
            float4 b0 = *(const float4*)&Bs[k][tx * 4];
            float am[8] = {a0.x, a0.y, a0.z, a0.w, a1.x, a1.y, a1.z, a1.w};
            float bn[4] = {b0.x, b0.y, b0.z, b0.w};
            #pragma unroll
            for (int i = 0; i < 8; i++)
                #pragma unroll
                for (int j = 0; j < 4; j++)
                    acc[i][j] = fmaf(am[i], bn[j], acc[i][j]);
        }
        __syncthreads();
    }

    #pragma unroll
    for (int i = 0; i < 8; i++) {
        int m = m0 + ty * 8 + i;
        #pragma unroll
        for (int j = 0; j < 4; j++) {
            int n = n0 + tx * 4 + j;
            float v = acc[i][j] + bias[n];
            if (TANH) v = tanhf(v);
            C[(long)m * ldc + n] = v;
        }
    }
}

// ---------------------------------------------------------------------------
// fused copy+scatter: one warp per table row (float4 lanes), winner row gets
// the freshly computed RNN output, everything else is a straight copy
__global__ void finalize_kernel(const float* __restrict__ dynU, const float* __restrict__ dynI,
                                const float* __restrict__ isU, const float* __restrict__ isI,
                                float* __restrict__ out) {
    int row = blockIdx.x * 8 + (threadIdx.x >> 5);
    int lane = threadIdx.x & 31;
    if (row < NU) {
        int w = g_winner_u[row];
        const float* src = (w >= 0) ? out + OFF_UPD_USER + (long)w * D
                                    : dynU + (long)row * D;
        float4 v = *(const float4*)(src + lane * 4);
        *(float4*)(out + OFF_DYN_USER + (long)row * D + lane * 4) = v;
        if (lane == 0) out[OFF_ISNEW_U + row] = (w >= 0) ? 0.f : isU[row];
    } else {
        int r = row - NU;
        if (r < NI) {
            int w = g_winner_i[r];
            const float* src = (w >= 0) ? out + OFF_UPD_ITEM + (long)w * D
                                        : dynI + (long)r * D;
            float4 v = *(const float4*)(src + lane * 4);
            *(float4*)(out + OFF_DYN_ITEM + (long)r * D + lane * 4) = v;
            if (lane == 0) out[OFF_ISNEW_I + r] = (w >= 0) ? 0.f : isI[r];
        }
    }
}

// ---------------------------------------------------------------------------
extern "C" void kernel_launch(void* const* d_in, const int* in_sizes, int n_in,
                              void* d_out, int out_size) {
    const int*   uid   = (const int*)d_in[0];
    const int*   pid   = (const int*)d_in[1];
    const int*   iid   = (const int*)d_in[2];
    const float* tItem = (const float*)d_in[3];
    const float* tUser = (const float*)d_in[4];
    const float* dynU  = (const float*)d_in[5];
    const float* dynI  = (const float*)d_in[6];
    const float* isU   = (const float*)d_in[7];
    const float* isI   = (const float*)d_in[8];
    const float* statU = (const float*)d_in[9];
    const float* statI = (const float*)d_in[10];
    const float* initU = (const float*)d_in[11];
    const float* initI = (const float*)d_in[12];
    const float* uWih  = (const float*)d_in[13];
    const float* uWhh  = (const float*)d_in[14];
    const float* ubih  = (const float*)d_in[15];
    const float* ubhh  = (const float*)d_in[16];
    const float* iWih  = (const float*)d_in[17];
    const float* iWhh  = (const float*)d_in[18];
    const float* ibih  = (const float*)d_in[19];
    const float* ibhh  = (const float*)d_in[20];
    const float* predW = (const float*)d_in[21];
    const float* predb = (const float*)d_in[22];
    const float* tdW   = (const float*)d_in[23];
    const float* tdb   = (const float*)d_in[24];
    float* out = (float*)d_out;

    float *xpred, *xu, *xi, *wu, *wi, *bu, *bi;
    cudaGetSymbolAddress((void**)&xpred, g_Xpred);
    cudaGetSymbolAddress((void**)&xu, g_Xu);
    cudaGetSymbolAddress((void**)&xi, g_Xi);
    cudaGetSymbolAddress((void**)&wu, g_Wu);
    cudaGetSymbolAddress((void**)&wi, g_Wi);
    cudaGetSymbolAddress((void**)&bu, g_bu);
    cudaGetSymbolAddress((void**)&bi, g_bi);

    reset_kernel<<<(NU + 255) / 256, 256>>>();
    prep_kernel<<<(D * KRNN + 255) / 256, 256>>>(uWih, uWhh, ubih, ubhh,
                                                 iWih, iWhh, ibih, ibhh);
    gather_kernel<<<B, 128>>>(uid, pid, iid, tItem, tUser, dynU, dynI, isU, isI,
                              statU, statI, initU, initI, tdW, tdb, out);

    // pred: 4096x256 = (4096x512) @ predW^T
    gemm_kernel<512, false><<<dim3(32, 4), 256>>>(xpred, predW, predb, out + OFF_PRED, 256);
    // RNN cells: tanh((4096x264) @ Wcat^T + b)
    gemm_kernel<KRNN, true><<<dim3(32, 2), 256>>>(xu, wu, bu, out + OFF_UPD_USER, 128);
    gemm_kernel<KRNN, true><<<dim3(32, 2), 256>>>(xi, wi, bi, out + OFF_UPD_ITEM, 128);

    finalize_kernel<<<(NU + NI) / 8, 256>>>(dynU, dynI, isU, isI, out);
}

// round 2
// speedup vs baseline: 1.1971x; 1.1971x over previous
#include <cuda_runtime.h>
#include <math.h>

#define NU 200000
#define NI 200000
#define D  128
#define B  4096
#define KRNN 264   // [x(129) | h(128) | pad(7)] ; 264 = 33*8

// ---- output layout (flattened tuple, row-major) ----
#define OFF_PRED       0
#define OFF_TARGET     (B*2*D)
#define OFF_UPD_USER   (OFF_TARGET + B*2*D)
#define OFF_USER_EMB   (OFF_UPD_USER + B*D)
#define OFF_UPD_ITEM   (OFF_USER_EMB + B*D)
#define OFF_ITEM_EMB   (OFF_UPD_ITEM + B*D)
#define OFF_DYN_USER   (OFF_ITEM_EMB + B*D)
#define OFF_DYN_ITEM   (OFF_DYN_USER + NU*D)
#define OFF_ISNEW_U    (OFF_DYN_ITEM + NI*D)
#define OFF_ISNEW_I    (OFF_ISNEW_U + NU)

// ---- device scratch ----
__device__ __align__(16) float g_Xpred[B * 512];
__device__ __align__(16) float g_Xu[B * KRNN];
__device__ __align__(16) float g_Xi[B * KRNN];
__device__ __align__(16) float g_Wu[D * KRNN];
__device__ __align__(16) float g_Wi[D * KRNN];
__device__ float g_bu[D];
__device__ float g_bi[D];
__device__ int g_winner_u[NU];
__device__ int g_winner_i[NI];

// ---- packed f32x2 helpers ----
#define FFMA2(c, a, b) asm("fma.rn.f32x2 %0, %1, %2, %3;" \
    : "=l"(c) : "l"(a), "l"(b), "l"(c))
#define PACK2(d, x, y) asm("mov.b64 %0, {%1, %2};" : "=l"(d) : "f"(x), "f"(y))
#define UNPACK2(lo, hi, v) asm("mov.b64 {%0, %1}, %2;" : "=f"(lo), "=f"(hi) : "l"(v))

// ---------------------------------------------------------------------------
__global__ void reset_kernel() {
    int i = blockIdx.x * blockDim.x + threadIdx.x;
    if (i < NU) { g_winner_u[i] = -1; g_winner_i[i] = -1; }
}

// last occurrence wins (CPU scatter order)
__global__ void winner_kernel(const int* __restrict__ uid, const int* __restrict__ iid) {
    int b = blockIdx.x * blockDim.x + threadIdx.x;
    if (b < B) {
        atomicMax(&g_winner_u[uid[b]], b);
        atomicMax(&g_winner_i[iid[b]], b);
    }
}

// build combined RNN weights [Wih | Whh | 0] and fused biases
__global__ void prep_kernel(const float* __restrict__ uWih, const float* __restrict__ uWhh,
                            const float* __restrict__ ubih, const float* __restrict__ ubhh,
                            const float* __restrict__ iWih, const float* __restrict__ iWhh,
                            const float* __restrict__ ibih, const float* __restrict__ ibhh) {
    int i = blockIdx.x * blockDim.x + threadIdx.x;
    if (i < D * KRNN) {
        int n = i / KRNN, k = i % KRNN;
        float wu, wi;
        if (k < 129)      { wu = uWih[n * 129 + k];       wi = iWih[n * 129 + k]; }
        else if (k < 257) { wu = uWhh[n * 128 + (k-129)]; wi = iWhh[n * 128 + (k-129)]; }
        else              { wu = 0.f; wi = 0.f; }
        g_Wu[i] = wu; g_Wi[i] = wi;
    }
    if (i < D) { g_bu[i] = ubih[i] + ubhh[i]; g_bi[i] = ibih[i] + ibhh[i]; }
}

// ---------------------------------------------------------------------------
__global__ void gather_kernel(const int* __restrict__ uid, const int* __restrict__ pid,
                              const int* __restrict__ iid,
                              const float* __restrict__ t_item, const float* __restrict__ t_user,
                              const float* __restrict__ dynU, const float* __restrict__ dynI,
                              const float* __restrict__ isU, const float* __restrict__ isI,
                              const float* __restrict__ statU, const float* __restrict__ statI,
                              const float* __restrict__ initU, const float* __restrict__ initI,
                              const float* __restrict__ tdW, const float* __restrict__ tdb,
                              float* __restrict__ out) {
    int b = blockIdx.x;
    int d = threadIdx.x;           // 0..127
    int u = uid[b], p = pid[b], it = iid[b];
    float ti = t_item[b], tu = t_user[b];
    float fu = isU[u], fi = isI[it], fp = isI[p];

    float ue = fu * initU[d] + dynU[(long)u * D + d];
    float ie = fi * initI[d] + dynI[(long)it * D + d];
    float pe = fp * initI[d] + dynI[(long)p * D + d];
    float su = statU[(long)u * D + d];
    float si = statI[(long)it * D + d];
    float ps = statI[(long)p * D + d];

    out[OFF_USER_EMB + b * D + d] = ue;
    out[OFF_ITEM_EMB + b * D + d] = ie;
    out[OFF_TARGET + b * 2 * D + d]     = ie;
    out[OFF_TARGET + b * 2 * D + D + d] = si;

    float proj = ue * (1.f + ti * tdW[d] + tdb[d]);
    g_Xpred[b * 512 + d]       = proj;
    g_Xpred[b * 512 + 128 + d] = pe;
    g_Xpred[b * 512 + 256 + d] = ps;
    g_Xpred[b * 512 + 384 + d] = su;

    g_Xu[b * KRNN + d]       = ie;
    g_Xu[b * KRNN + 129 + d] = ue;
    g_Xi[b * KRNN + d]       = ue;
    g_Xi[b * KRNN + 129 + d] = ie;
    if (d == 0) {
        g_Xu[b * KRNN + 128] = ti;
        g_Xi[b * KRNN + 128] = tu;
    }
    if (d < KRNN - 257) {
        g_Xu[b * KRNN + 257 + d] = 0.f;
        g_Xi[b * KRNN + 257 + d] = 0.f;
    }
}

// ---------------------------------------------------------------------------
// C[m][n] = act( sum_k X[m][k]*W[n][k] + bias[n] )
// tile 128(M) x 64(N), BK=8, 256 threads, 8x4 microtile, f32x2 packed FMA,
// double-buffered smem (single sync per K-tile)
template <int KDIM, bool TANH>
__global__ void gemm_kernel(const float* __restrict__ X, const float* __restrict__ W,
                            const float* __restrict__ bias, float* __restrict__ C, int ldc) {
    __shared__ __align__(16) float As[2][8][128];
    __shared__ __align__(16) float Bs[2][8][64];
    int tid = threadIdx.x;
    int m0 = blockIdx.x * 128;
    int n0 = blockIdx.y * 64;
    int tx = tid & 15;        // N dir (x4)
    int ty = tid >> 4;        // M dir (x8, as 4 f32x2 pairs)

    unsigned long long acc[4][4];
    #pragma unroll
    for (int i = 0; i < 4; i++)
        #pragma unroll
        for (int j = 0; j < 4; j++) acc[i][j] = 0ull;

    int arow = tid >> 1;            // 0..127
    int acol = (tid & 1) * 4;       // 0 or 4
    const float* Aptr = X + (long)(m0 + arow) * KDIM + acol;
    const float* Bptr = W + (long)(n0 + arow) * KDIM + acol;  // only tid<128 valid
    const int KT = KDIM / 8;

    // preload tile 0
    float4 av = *(const float4*)Aptr;
    float4 bv = make_float4(0.f, 0.f, 0.f, 0.f);
    if (tid < 128) bv = *(const float4*)Bptr;
    As[0][acol + 0][arow] = av.x; As[0][acol + 1][arow] = av.y;
    As[0][acol + 2][arow] = av.z; As[0][acol + 3][arow] = av.w;
    if (tid < 128) {
        Bs[0][acol + 0][arow] = bv.x; Bs[0][acol + 1][arow] = bv.y;
        Bs[0][acol + 2][arow] = bv.z; Bs[0][acol + 3][arow] = bv.w;
    }
    __syncthreads();

    int buf = 0;
    for (int kt = 0; kt < KT; kt++) {
        if (kt + 1 < KT) {
            av = *(const float4*)(Aptr + (kt + 1) * 8);
            if (tid < 128) bv = *(const float4*)(Bptr + (kt + 1) * 8);
        }
        #pragma unroll
        for (int k = 0; k < 8; k++) {
            float4 a0 = *(const float4*)&As[buf][k][ty * 8];
            float4 a1 = *(const float4*)&As[buf][k][ty * 8 + 4];
            float4 b0 = *(const float4*)&Bs[buf][k][tx * 4];
            unsigned long long aa[4], bb[4];
            PACK2(aa[0], a0.x, a0.y); PACK2(aa[1], a0.z, a0.w);
            PACK2(aa[2], a1.x, a1.y); PACK2(aa[3], a1.z, a1.w);
            PACK2(bb[0], b0.x, b0.x); PACK2(bb[1], b0.y, b0.y);
            PACK2(bb[2], b0.z, b0.z); PACK2(bb[3], b0.w, b0.w);
            #pragma unroll
            for (int i = 0; i < 4; i++)
                #pragma unroll
                for (int j = 0; j < 4; j++)
                    FFMA2(acc[i][j], aa[i], bb[j]);
        }
        if (kt + 1 < KT) {
            buf ^= 1;
            As[buf][acol + 0][arow] = av.x; As[buf][acol + 1][arow] = av.y;
            As[buf][acol + 2][arow] = av.z; As[buf][acol + 3][arow] = av.w;
            if (tid < 128) {
                Bs[buf][acol + 0][arow] = bv.x; Bs[buf][acol + 1][arow] = bv.y;
                Bs[buf][acol + 2][arow] = bv.z; Bs[buf][acol + 3][arow] = bv.w;
            }
            __syncthreads();
        }
    }

    float4 bias4 = *(const float4*)&bias[n0 + tx * 4];
    float bn[4] = {bias4.x, bias4.y, bias4.z, bias4.w};
    #pragma unroll
    for (int p = 0; p < 4; p++) {
        int mlo = m0 + ty * 8 + 2 * p;
        float lo[4], hi[4];
        #pragma unroll
        for (int j = 0; j < 4; j++) {
            float l, h;
            UNPACK2(l, h, acc[p][j]);
            l += bn[j]; h += bn[j];
            if (TANH) { l = tanhf(l); h = tanhf(h); }
            lo[j] = l; hi[j] = h;
        }
        *(float4*)&C[(long)mlo * ldc + n0 + tx * 4]       = make_float4(lo[0], lo[1], lo[2], lo[3]);
        *(float4*)&C[(long)(mlo + 1) * ldc + n0 + tx * 4] = make_float4(hi[0], hi[1], hi[2], hi[3]);
    }
}

// ---------------------------------------------------------------------------
// big table copy (skips winner rows; scatter_kernel writes those later)
__global__ void copy_kernel(const float* __restrict__ dynU, const float* __restrict__ dynI,
                            const float* __restrict__ isU, const float* __restrict__ isI,
                            float* __restrict__ out) {
    int row = blockIdx.x * 8 + (threadIdx.x >> 5);
    int lane = threadIdx.x & 31;
    if (row < NU) {
        int w = g_winner_u[row];
        if (lane == 0) out[OFF_ISNEW_U + row] = (w >= 0) ? 0.f : isU[row];
        if (w < 0) {
            float4 v = *(const float4*)(dynU + (long)row * D + lane * 4);
            *(float4*)(out + OFF_DYN_USER + (long)row * D + lane * 4) = v;
        }
    } else {
        int r = row - NU;
        if (r < NI) {
            int w = g_winner_i[r];
            if (lane == 0) out[OFF_ISNEW_I + r] = (w >= 0) ? 0.f : isI[r];
            if (w < 0) {
                float4 v = *(const float4*)(dynI + (long)r * D + lane * 4);
                *(float4*)(out + OFF_DYN_ITEM + (long)r * D + lane * 4) = v;
            }
        }
    }
}

// write updated embeddings into winner rows
__global__ void scatter_kernel(const int* __restrict__ uid, const int* __restrict__ iid,
                               float* __restrict__ out) {
    int gw = blockIdx.x * 8 + (threadIdx.x >> 5);
    int lane = threadIdx.x & 31;
    if (gw < B) {
        int id = uid[gw];
        if (g_winner_u[id] == gw) {
            float4 v = *(const float4*)(out + OFF_UPD_USER + (long)gw * D + lane * 4);
            *(float4*)(out + OFF_DYN_USER + (long)id * D + lane * 4) = v;
        }
    } else {
        int b = gw - B;
        if (b < B) {
            int id = iid[b];
            if (g_winner_i[id] == b) {
                float4 v = *(const float4*)(out + OFF_UPD_ITEM + (long)b * D + lane * 4);
                *(float4*)(out + OFF_DYN_ITEM + (long)id * D + lane * 4) = v;
            }
        }
    }
}

// ---------------------------------------------------------------------------
extern "C" void kernel_launch(void* const* d_in, const int* in_sizes, int n_in,
                              void* d_out, int out_size) {
    const int*   uid   = (const int*)d_in[0];
    const int*   pid   = (const int*)d_in[1];
    const int*   iid   = (const int*)d_in[2];
    const float* tItem = (const float*)d_in[3];
    const float* tUser = (const float*)d_in[4];
    const float* dynU  = (const float*)d_in[5];
    const float* dynI  = (const float*)d_in[6];
    const float* isU   = (const float*)d_in[7];
    const float* isI   = (const float*)d_in[8];
    const float* statU = (const float*)d_in[9];
    const float* statI = (const float*)d_in[10];
    const float* initU = (const float*)d_in[11];
    const float* initI = (const float*)d_in[12];
    const float* uWih  = (const float*)d_in[13];
    const float* uWhh  = (const float*)d_in[14];
    const float* ubih  = (const float*)d_in[15];
    const float* ubhh  = (const float*)d_in[16];
    const float* iWih  = (const float*)d_in[17];
    const float* iWhh  = (const float*)d_in[18];
    const float* ibih  = (const float*)d_in[19];
    const float* ibhh  = (const float*)d_in[20];
    const float* predW = (const float*)d_in[21];
    const float* predb = (const float*)d_in[22];
    const float* tdW   = (const float*)d_in[23];
    const float* tdb   = (const float*)d_in[24];
    float* out = (float*)d_out;

    float *xpred, *xu, *xi, *wu, *wi, *bu, *bi;
    cudaGetSymbolAddress((void**)&xpred, g_Xpred);
    cudaGetSymbolAddress((void**)&xu, g_Xu);
    cudaGetSymbolAddress((void**)&xi, g_Xi);
    cudaGetSymbolAddress((void**)&wu, g_Wu);
    cudaGetSymbolAddress((void**)&wi, g_Wi);
    cudaGetSymbolAddress((void**)&bu, g_bu);
    cudaGetSymbolAddress((void**)&bi, g_bi);

    static cudaStream_t sCopy = nullptr, sRnn = nullptr;
    static cudaEvent_t evW = nullptr, evG = nullptr, evCopy = nullptr, evRnn = nullptr;
    if (!sCopy) {
        cudaStreamCreateWithFlags(&sCopy, cudaStreamNonBlocking);
        cudaStreamCreateWithFlags(&sRnn, cudaStreamNonBlocking);
        cudaEventCreateWithFlags(&evW, cudaEventDisableTiming);
        cudaEventCreateWithFlags(&evG, cudaEventDisableTiming);
        cudaEventCreateWithFlags(&evCopy, cudaEventDisableTiming);
        cudaEventCreateWithFlags(&evRnn, cudaEventDisableTiming);
    }

    // stream 0: winner info ASAP, then fork the big copy
    reset_kernel<<<(NU + 255) / 256, 256>>>();
    winner_kernel<<<(B + 255) / 256, 256>>>(uid, iid);
    cudaEventRecord(evW, 0);
    cudaStreamWaitEvent(sCopy, evW, 0);
    copy_kernel<<<(NU + NI) / 8, 256, 0, sCopy>>>(dynU, dynI, isU, isI, out);
    cudaEventRecord(evCopy, sCopy);

    // stream 0: prep + gather, fork RNN gemms, run pred gemm
    prep_kernel<<<(D * KRNN + 255) / 256, 256>>>(uWih, uWhh, ubih, ubhh,
                                                 iWih, iWhh, ibih, ibhh);
    gather_kernel<<<B, 128>>>(uid, pid, iid, tItem, tUser, dynU, dynI, isU, isI,
                              statU, statI, initU, initI, tdW, tdb, out);
    cudaEventRecord(evG, 0);
    cudaStreamWaitEvent(sRnn, evG, 0);
    gemm_kernel<KRNN, true><<<dim3(32, 2), 256, 0, sRnn>>>(xu, wu, bu, out + OFF_UPD_USER, 128);
    gemm_kernel<KRNN, true><<<dim3(32, 2), 256, 0, sRnn>>>(xi, wi, bi, out + OFF_UPD_ITEM, 128);
    cudaEventRecord(evRnn, sRnn);

    gemm_kernel<512, false><<<dim3(32, 4), 256>>>(xpred, predW, predb, out + OFF_PRED, 256);

    // join: scatter winner rows after copy + RNN outputs are ready
    cudaStreamWaitEvent(0, evCopy, 0);
    cudaStreamWaitEvent(0, evRnn, 0);
    scatter_kernel<<<(2 * B) / 8, 256>>>(uid, iid, out);
}

// round 3
// speedup vs baseline: 1.4246x; 1.1900x over previous
#include <cuda_runtime.h>
#include <math.h>

#define NU 200000
#define NI 200000
#define D  128
#define B  4096
#define KRNN 264   // [x(129) | h(128) | pad(7)] ; 264 = 33*8

// ---- output layout (flattened tuple, row-major) ----
#define OFF_PRED       0
#define OFF_TARGET     (B*2*D)
#define OFF_UPD_USER   (OFF_TARGET + B*2*D)
#define OFF_USER_EMB   (OFF_UPD_USER + B*D)
#define OFF_UPD_ITEM   (OFF_USER_EMB + B*D)
#define OFF_ITEM_EMB   (OFF_UPD_ITEM + B*D)
#define OFF_DYN_USER   (OFF_ITEM_EMB + B*D)
#define OFF_DYN_ITEM   (OFF_DYN_USER + NU*D)
#define OFF_ISNEW_U    (OFF_DYN_ITEM + NI*D)
#define OFF_ISNEW_I    (OFF_ISNEW_U + NU)

// ---- device scratch ----
__device__ __align__(16) float g_Xpred[B * 512];
__device__ __align__(16) float g_Xu[B * KRNN];
__device__ __align__(16) float g_Xi[B * KRNN];
__device__ __align__(16) float g_Wu[D * KRNN];
__device__ __align__(16) float g_Wi[D * KRNN];
__device__ float g_bu[D];
__device__ float g_bi[D];
__device__ int g_winner_u[NU];
__device__ int g_winner_i[NI];

typedef unsigned long long ull;
#define FFMA2(c, a, b) asm("fma.rn.f32x2 %0, %1, %2, %3;" \
    : "=l"(c) : "l"(a), "l"(b), "l"(c))
#define PACK2(d, x, y) asm("mov.b64 %0, {%1, %2};" : "=l"(d) : "f"(x), "f"(y))
#define UNPACK2(lo, hi, v) asm("mov.b64 {%0, %1}, %2;" : "=f"(lo), "=f"(hi) : "l"(v))

// ---------------------------------------------------------------------------
__global__ void reset_kernel() {
    int i = blockIdx.x * blockDim.x + threadIdx.x;
    if (i < NU) { g_winner_u[i] = -1; g_winner_i[i] = -1; }
}

// last occurrence wins (CPU scatter order)
__global__ void winner_kernel(const int* __restrict__ uid, const int* __restrict__ iid) {
    int b = blockIdx.x * blockDim.x + threadIdx.x;
    if (b < B) {
        atomicMax(&g_winner_u[uid[b]], b);
        atomicMax(&g_winner_i[iid[b]], b);
    }
}

__global__ void isnew_kernel(const float* __restrict__ isU, const float* __restrict__ isI,
                             float* __restrict__ out) {
    int i = blockIdx.x * blockDim.x + threadIdx.x;
    if (i < NU) {
        out[OFF_ISNEW_U + i] = (g_winner_u[i] >= 0) ? 0.f : isU[i];
    } else {
        int r = i - NU;
        if (r < NI) out[OFF_ISNEW_I + r] = (g_winner_i[r] >= 0) ? 0.f : isI[r];
    }
}

// build combined RNN weights [Wih | Whh | 0] and fused biases
__global__ void prep_kernel(const float* __restrict__ uWih, const float* __restrict__ uWhh,
                            const float* __restrict__ ubih, const float* __restrict__ ubhh,
                            const float* __restrict__ iWih, const float* __restrict__ iWhh,
                            const float* __restrict__ ibih, const float* __restrict__ ibhh) {
    int i = blockIdx.x * blockDim.x + threadIdx.x;
    if (i < D * KRNN) {
        int n = i / KRNN, k = i % KRNN;
        float wu, wi;
        if (k < 129)      { wu = uWih[n * 129 + k];       wi = iWih[n * 129 + k]; }
        else if (k < 257) { wu = uWhh[n * 128 + (k-129)]; wi = iWhh[n * 128 + (k-129)]; }
        else              { wu = 0.f; wi = 0.f; }
        g_Wu[i] = wu; g_Wi[i] = wi;
    }
    if (i < D) { g_bu[i] = ubih[i] + ubhh[i]; g_bi[i] = ibih[i] + ibhh[i]; }
}

// ---------------------------------------------------------------------------
__global__ void gather_kernel(const int* __restrict__ uid, const int* __restrict__ pid,
                              const int* __restrict__ iid,
                              const float* __restrict__ t_item, const float* __restrict__ t_user,
                              const float* __restrict__ dynU, const float* __restrict__ dynI,
                              const float* __restrict__ isU, const float* __restrict__ isI,
                              const float* __restrict__ statU, const float* __restrict__ statI,
                              const float* __restrict__ initU, const float* __restrict__ initI,
                              const float* __restrict__ tdW, const float* __restrict__ tdb,
                              float* __restrict__ out) {
    int b = blockIdx.x;
    int d = threadIdx.x;           // 0..127
    int u = uid[b], p = pid[b], it = iid[b];
    float ti = t_item[b], tu = t_user[b];
    float fu = isU[u], fi = isI[it], fp = isI[p];

    float ue = fu * initU[d] + dynU[(long)u * D + d];
    float ie = fi * initI[d] + dynI[(long)it * D + d];
    float pe = fp * initI[d] + dynI[(long)p * D + d];
    float su = statU[(long)u * D + d];
    float si = statI[(long)it * D + d];
    float ps = statI[(long)p * D + d];

    out[OFF_USER_EMB + b * D + d] = ue;
    out[OFF_ITEM_EMB + b * D + d] = ie;
    out[OFF_TARGET + b * 2 * D + d]     = ie;
    out[OFF_TARGET + b * 2 * D + D + d] = si;

    float proj = ue * (1.f + ti * tdW[d] + tdb[d]);
    g_Xpred[b * 512 + d]       = proj;
    g_Xpred[b * 512 + 128 + d] = pe;
    g_Xpred[b * 512 + 256 + d] = ps;
    g_Xpred[b * 512 + 384 + d] = su;

    g_Xu[b * KRNN + d]       = ie;
    g_Xu[b * KRNN + 129 + d] = ue;
    g_Xi[b * KRNN + d]       = ue;
    g_Xi[b * KRNN + 129 + d] = ie;
    if (d == 0) {
        g_Xu[b * KRNN + 128] = ti;
        g_Xi[b * KRNN + 128] = tu;
    }
    if (d < KRNN - 257) {
        g_Xu[b * KRNN + 257 + d] = 0.f;
        g_Xi[b * KRNN + 257 + d] = 0.f;
    }
}

// ---------------------------------------------------------------------------
// C[m][n] = act( sum_k X[m][k]*W[n][k] + bias[n] )
// tile 64(M) x 64(N), BK=8, 256 threads, 4x4 microtile (M as 2 f32x2 pairs),
// double-buffered smem, packed FFMA2 (A pairs come packed straight from smem)
template <int KDIM, bool TANH>
__device__ __forceinline__ void gemm64_body(const float* __restrict__ X,
                                            const float* __restrict__ W,
                                            const float* __restrict__ bias,
                                            float* __restrict__ C, int ldc) {
    __shared__ __align__(16) float As[2][8][64];
    __shared__ __align__(16) float Bs[2][8][64];
    int tid = threadIdx.x;
    int m0 = blockIdx.x * 64;
    int n0 = blockIdx.y * 64;
    int tx = tid & 15;        // N dir (x4)
    int ty = tid >> 4;        // M dir (x4 = 2 f32x2 pairs)

    ull acc[2][4];
    #pragma unroll
    for (int i = 0; i < 2; i++)
        #pragma unroll
        for (int j = 0; j < 4; j++) acc[i][j] = 0ull;

    int lrow = (tid & 127) >> 1;      // 0..63
    int lcol = (tid & 1) * 4;         // 0 or 4
    bool loadA = tid < 128;
    const float* src = loadA ? X + (long)(m0 + lrow) * KDIM + lcol
                             : W + (long)(n0 + lrow) * KDIM + lcol;
    const int KT = KDIM / 8;

    float4 v = *(const float4*)src;
    {
        float (*dst)[64] = loadA ? As[0] : Bs[0];
        dst[lcol + 0][lrow] = v.x; dst[lcol + 1][lrow] = v.y;
        dst[lcol + 2][lrow] = v.z; dst[lcol + 3][lrow] = v.w;
    }
    __syncthreads();

    int buf = 0;
    for (int kt = 0; kt < KT; kt++) {
        if (kt + 1 < KT) v = *(const float4*)(src + (kt + 1) * 8);
        #pragma unroll
        for (int k = 0; k < 8; k++) {
            ulonglong2 a = *(const ulonglong2*)&As[buf][k][ty * 4];
            float4 b0 = *(const float4*)&Bs[buf][k][tx * 4];
            ull bb[4];
            PACK2(bb[0], b0.x, b0.x); PACK2(bb[1], b0.y, b0.y);
            PACK2(bb[2], b0.z, b0.z); PACK2(bb[3], b0.w, b0.w);
            #pragma unroll
            for (int j = 0; j < 4; j++) {
                FFMA2(acc[0][j], a.x, bb[j]);
                FFMA2(acc[1][j], a.y, bb[j]);
            }
        }
        if (kt + 1 < KT) {
            buf ^= 1;
            float (*dst)[64] = loadA ? As[buf] : Bs[buf];
            dst[lcol + 0][lrow] = v.x; dst[lcol + 1][lrow] = v.y;
            dst[lcol + 2][lrow] = v.z; dst[lcol + 3][lrow] = v.w;
            __syncthreads();
        }
    }

    float4 bias4 = *(const float4*)&bias[n0 + tx * 4];
    float bn[4] = {bias4.x, bias4.y, bias4.z, bias4.w};
    #pragma unroll
    for (int p = 0; p < 2; p++) {
        int mlo = m0 + ty * 4 + 2 * p;
        float lo[4], hi[4];
        #pragma unroll
        for (int j = 0; j < 4; j++) {
            float l, h;
            UNPACK2(l, h, acc[p][j]);
            l += bn[j]; h += bn[j];
            if (TANH) { l = tanhf(l); h = tanhf(h); }
            lo[j] = l; hi[j] = h;
        }
        *(float4*)&C[(long)mlo * ldc + n0 + tx * 4]       = make_float4(lo[0], lo[1], lo[2], lo[3]);
        *(float4*)&C[(long)(mlo + 1) * ldc + n0 + tx * 4] = make_float4(hi[0], hi[1], hi[2], hi[3]);
    }
}

__global__ void __launch_bounds__(256) pred_gemm_kernel(const float* __restrict__ X,
                                                        const float* __restrict__ W,
                                                        const float* __restrict__ bias,
                                                        float* __restrict__ C) {
    gemm64_body<512, false>(X, W, bias, C, 256);
}

// both RNN cells in one launch: z=0 -> user, z=1 -> item
__global__ void __launch_bounds__(256) rnn_gemm_kernel(float* __restrict__ out) {
    if (blockIdx.z == 0)
        gemm64_body<KRNN, true>(g_Xu, g_Wu, g_bu, out + OFF_UPD_USER, 128);
    else
        gemm64_body<KRNN, true>(g_Xi, g_Wi, g_bi, out + OFF_UPD_ITEM, 128);
}

// ---------------------------------------------------------------------------
// overwrite winner rows of the copied tables with updated embeddings
__global__ void scatter_kernel(const int* __restrict__ uid, const int* __restrict__ iid,
                               float* __restrict__ out) {
    int gw = blockIdx.x * 8 + (threadIdx.x >> 5);
    int lane = threadIdx.x & 31;
    if (gw < B) {
        int id = uid[gw];
        if (g_winner_u[id] == gw) {
            float4 v = *(const float4*)(out + OFF_UPD_USER + (long)gw * D + lane * 4);
            *(float4*)(out + OFF_DYN_USER + (long)id * D + lane * 4) = v;
        }
    } else {
        int b = gw - B;
        if (b < B) {
            int id = iid[b];
            if (g_winner_i[id] == b) {
                float4 v = *(const float4*)(out + OFF_UPD_ITEM + (long)b * D + lane * 4);
                *(float4*)(out + OFF_DYN_ITEM + (long)id * D + lane * 4) = v;
            }
        }
    }
}

// ---------------------------------------------------------------------------
extern "C" void kernel_launch(void* const* d_in, const int* in_sizes, int n_in,
                              void* d_out, int out_size) {
    const int*   uid   = (const int*)d_in[0];
    const int*   pid   = (const int*)d_in[1];
    const int*   iid   = (const int*)d_in[2];
    const float* tItem = (const float*)d_in[3];
    const float* tUser = (const float*)d_in[4];
    const float* dynU  = (const float*)d_in[5];
    const float* dynI  = (const float*)d_in[6];
    const float* isU   = (const float*)d_in[7];
    const float* isI   = (const float*)d_in[8];
    const float* statU = (const float*)d_in[9];
    const float* statI = (const float*)d_in[10];
    const float* initU = (const float*)d_in[11];
    const float* initI = (const float*)d_in[12];
    const float* uWih  = (const float*)d_in[13];
    const float* uWhh  = (const float*)d_in[14];
    const float* ubih  = (const float*)d_in[15];
    const float* ubhh  = (const float*)d_in[16];
    const float* iWih  = (const float*)d_in[17];
    const float* iWhh  = (const float*)d_in[18];
    const float* ibih  = (const float*)d_in[19];
    const float* ibhh  = (const float*)d_in[20];
    const float* predW = (const float*)d_in[21];
    const float* predb = (const float*)d_in[22];
    const float* tdW   = (const float*)d_in[23];
    const float* tdb   = (const float*)d_in[24];
    float* out = (float*)d_out;

    float *xpred;
    cudaGetSymbolAddress((void**)&xpred, g_Xpred);

    static cudaStream_t sCopy = nullptr, sRnn = nullptr;
    static cudaEvent_t evStart = nullptr, evG = nullptr, evCopy = nullptr, evRnn = nullptr;
    if (!sCopy) {
        cudaStreamCreateWithFlags(&sCopy, cudaStreamNonBlocking);
        cudaStreamCreateWithFlags(&sRnn, cudaStreamNonBlocking);
        cudaEventCreateWithFlags(&evStart, cudaEventDisableTiming);
        cudaEventCreateWithFlags(&evG, cudaEventDisableTiming);
        cudaEventCreateWithFlags(&evCopy, cudaEventDisableTiming);
        cudaEventCreateWithFlags(&evRnn, cudaEventDisableTiming);
    }

    // fork immediately: bulk table copy (winner-independent; winners patched later)
    cudaEventRecord(evStart, 0);
    cudaStreamWaitEvent(sCopy, evStart, 0);
    cudaMemcpyAsync(out + OFF_DYN_USER, dynU, (size_t)NU * D * sizeof(float),
                    cudaMemcpyDeviceToDevice, sCopy);
    cudaMemcpyAsync(out + OFF_DYN_ITEM, dynI, (size_t)NI * D * sizeof(float),
                    cudaMemcpyDeviceToDevice, sCopy);
    cudaEventRecord(evCopy, sCopy);

    // fork: RNN weight prep off the critical path
    cudaStreamWaitEvent(sRnn, evStart, 0);
    prep_kernel<<<(D * KRNN + 255) / 256, 256, 0, sRnn>>>(uWih, uWhh, ubih, ubhh,
                                                          iWih, iWhh, ibih, ibhh);

    // main stream: winners + isnew + gather + pred GEMM
    reset_kernel<<<(NU + 255) / 256, 256>>>();
    winner_kernel<<<(B + 255) / 256, 256>>>(uid, iid);
    isnew_kernel<<<(NU + NI + 255) / 256, 256>>>(isU, isI, out);
    gather_kernel<<<B, 128>>>(uid, pid, iid, tItem, tUser, dynU, dynI, isU, isI,
                              statU, statI, initU, initI, tdW, tdb, out);
    cudaEventRecord(evG, 0);

    cudaStreamWaitEvent(sRnn, evG, 0);
    rnn_gemm_kernel<<<dim3(64, 2, 2), 256, 0, sRnn>>>(out);
    cudaEventRecord(evRnn, sRnn);

    pred_gemm_kernel<<<dim3(64, 4), 256>>>(xpred, predW, predb, out + OFF_PRED);

    // join: patch winner rows once copy + RNN outputs exist
    cudaStreamWaitEvent(0, evCopy, 0);
    cudaStreamWaitEvent(0, evRnn, 0);
    scatter_kernel<<<(2 * B) / 8, 256>>>(uid, iid, out);
}